// round 1
// baseline (speedup 1.0000x reference)
#include <cuda_runtime.h>
#include <math.h>
#include <stdint.h>

// Problem constants
#define BB   2
#define RR   4096
#define SC   48
#define SFN  48
#define CF   32
#define RES  256
#define HID  64
#define ODIM 33          // 1 + OUT_DIM
#define NRAY  (BB*RR)    // 8192
#define NSAMP (NRAY*SC)  // 393216

__device__ __constant__ float RAY_START_F = 0.1f;
#define DELTA_F ((2.0f - 0.1f) / (float)(SC - 1))

// -------- device scratch (no allocations allowed) --------
__device__ float g_planes_t[(size_t)BB*3*RES*RES*CF]; // [b,p,y,x,c]
__device__ float g_depths_c[NSAMP];
__device__ float g_depths_f[NSAMP];
__device__ float g_sigma_c[NSAMP];
__device__ float g_sigma_f[NSAMP];
__device__ float g_rgb_c[(size_t)NSAMP*32];
__device__ float g_rgb_f[(size_t)NSAMP*32];

__device__ __forceinline__ float softplusf(float x) {
    // matches jax.nn.softplus = logaddexp(x, 0)
    return (x > 0.f) ? (x + log1pf(expf(-x))) : log1pf(expf(x));
}

// -------- transpose planes [b,p,c,y,x] -> [b,p,y,x,c] --------
__global__ void k_transpose(const float* __restrict__ in) {
    __shared__ float tile[32][33];
    int bp = blockIdx.z;
    int m0 = blockIdx.x * 32;          // m = y*RES + x
    int tx = threadIdx.x, ty = threadIdx.y;
    tile[ty][tx] = in[((size_t)bp*CF + ty)*(RES*RES) + m0 + tx];
    __syncthreads();
    g_planes_t[((size_t)bp*(RES*RES) + (m0 + ty))*CF + tx] = tile[tx][ty];
}

// -------- coarse stratified depths --------
__global__ void k_coarse_depths(const float* __restrict__ noise) {
    int i = blockIdx.x * blockDim.x + threadIdx.x;
    if (i >= NSAMP) return;
    int s = i % SC;
    g_depths_c[i] = RAY_START_F + (float)s * DELTA_F + noise[i] * DELTA_F;
}

// -------- model eval: gather tri-plane features + MLP --------
__global__ void __launch_bounds__(128) k_eval(
    const float* __restrict__ ro, const float* __restrict__ rd,
    const float* __restrict__ w1, const float* __restrict__ b1,
    const float* __restrict__ w2, const float* __restrict__ b2,
    int fine)
{
    __shared__ __align__(16) float sw1[CF*HID];
    __shared__ __align__(16) float sw2t[ODIM*HID];   // transposed [k][j]
    __shared__ __align__(16) float sb1[HID];
    __shared__ float sb2[ODIM];

    int tid = threadIdx.x;
    for (int i = tid; i < CF*HID; i += blockDim.x) sw1[i] = w1[i];
    for (int i = tid; i < HID*ODIM; i += blockDim.x) {
        int j = i / ODIM, k = i % ODIM;
        sw2t[k*HID + j] = w2[i];
    }
    for (int i = tid; i < HID;  i += blockDim.x) sb1[i] = b1[i];
    for (int i = tid; i < ODIM; i += blockDim.x) sb2[i] = b2[i];
    __syncthreads();

    int idx = blockIdx.x * blockDim.x + tid;
    if (idx >= NSAMP) return;

    const float* depths = fine ? g_depths_f : g_depths_c;
    float* sigma_out    = fine ? g_sigma_f  : g_sigma_c;
    float* rgb_out      = fine ? g_rgb_f    : g_rgb_c;

    int ray = idx / SC;
    int b   = ray / RR;

    float t  = depths[idx];
    float cc[3];
    cc[0] = (ro[ray*3+0] + t*rd[ray*3+0]) * 0.5f;
    cc[1] = (ro[ray*3+1] + t*rd[ray*3+1]) * 0.5f;
    cc[2] = (ro[ray*3+2] + t*rd[ray*3+2]) * 0.5f;

    float f[CF];
#pragma unroll
    for (int i = 0; i < CF; i++) f[i] = 0.f;

#pragma unroll
    for (int p = 0; p < 3; p++) {
        float gx = cc[p];
        float gy = cc[(p+1)%3];
        float x = ((gx + 1.f)*(float)RES - 1.f)*0.5f;
        float y = ((gy + 1.f)*(float)RES - 1.f)*0.5f;
        float x0f = floorf(x), y0f = floorf(y);
        float wx1 = x - x0f, wy1 = y - y0f;
        float wx0 = 1.f - wx1, wy0 = 1.f - wy1;
        int x0 = (int)x0f, y0 = (int)y0f;
        const float* base = g_planes_t + ((size_t)(b*3 + p))*((size_t)RES*RES*CF);
#pragma unroll
        for (int cy = 0; cy < 2; cy++) {
            int yy = y0 + cy;
            if (yy < 0 || yy >= RES) continue;
            float wy = cy ? wy1 : wy0;
#pragma unroll
            for (int cx = 0; cx < 2; cx++) {
                int xx = x0 + cx;
                if (xx < 0 || xx >= RES) continue;
                float w = wy * (cx ? wx1 : wx0);
                const float4* q = (const float4*)(base + ((size_t)yy*RES + xx)*CF);
#pragma unroll
                for (int j = 0; j < CF/4; j++) {
                    float4 v = q[j];
                    f[4*j+0] = fmaf(w, v.x, f[4*j+0]);
                    f[4*j+1] = fmaf(w, v.y, f[4*j+1]);
                    f[4*j+2] = fmaf(w, v.z, f[4*j+2]);
                    f[4*j+3] = fmaf(w, v.w, f[4*j+3]);
                }
            }
        }
    }
#pragma unroll
    for (int i = 0; i < CF; i++) f[i] *= (1.f/3.f);

    // layer 1: h = softplus(f @ w1 + b1)
    float h[HID];
    const float4* w14 = (const float4*)sw1;
    const float4* b14 = (const float4*)sb1;
#pragma unroll
    for (int jj = 0; jj < HID/4; jj++) {
        float4 a = b14[jj];
#pragma unroll
        for (int i = 0; i < CF; i++) {
            float4 wv = w14[i*(HID/4) + jj];
            a.x = fmaf(f[i], wv.x, a.x);
            a.y = fmaf(f[i], wv.y, a.y);
            a.z = fmaf(f[i], wv.z, a.z);
            a.w = fmaf(f[i], wv.w, a.w);
        }
        h[4*jj+0] = softplusf(a.x);
        h[4*jj+1] = softplusf(a.y);
        h[4*jj+2] = softplusf(a.z);
        h[4*jj+3] = softplusf(a.w);
    }

    // layer 2: o = h @ w2 + b2 ; sigma = o[0]; rgb = sigmoid(o[1:])*1.002 - 0.001
    float rgbl[32];
    const float4* w24 = (const float4*)sw2t;
#pragma unroll
    for (int k = 0; k < ODIM; k++) {
        float a = sb2[k];
#pragma unroll
        for (int j = 0; j < HID/4; j++) {
            float4 wv = w24[k*(HID/4) + j];
            a = fmaf(h[4*j+0], wv.x, a);
            a = fmaf(h[4*j+1], wv.y, a);
            a = fmaf(h[4*j+2], wv.z, a);
            a = fmaf(h[4*j+3], wv.w, a);
        }
        if (k == 0) {
            sigma_out[idx] = a;
        } else {
            float s = 1.f/(1.f + expf(-a));
            rgbl[k-1] = s*1.002f - 0.001f;
        }
    }

    float4* o4 = (float4*)(rgb_out + (size_t)idx*32);
#pragma unroll
    for (int j = 0; j < 8; j++)
        o4[j] = make_float4(rgbl[4*j], rgbl[4*j+1], rgbl[4*j+2], rgbl[4*j+3]);
}

// -------- coarse ray-march weights + inverse-CDF importance sampling --------
__global__ void k_importance(const float* __restrict__ noise_imp) {
    int ray = blockIdx.x * blockDim.x + threadIdx.x;
    if (ray >= NRAY) return;

    float d[SC], sg[SC];
    const float* dp  = g_depths_c + (size_t)ray*SC;
    const float* sgp = g_sigma_c  + (size_t)ray*SC;
#pragma unroll
    for (int i = 0; i < SC; i++) { d[i] = dp[i]; sg[i] = sgp[i]; }

    float w[SC-1];
    float T = 1.f;
#pragma unroll
    for (int i = 0; i < SC-1; i++) {
        float dens  = softplusf(0.5f*(sg[i] + sg[i+1]) - 1.f);
        float delta = d[i+1] - d[i];
        float alpha = 1.f - expf(-dens*delta);
        w[i] = alpha * T;
        T *= (1.f - alpha + 1e-10f);
    }

    // max-filter smoothing (wp padded with -inf)
    float m[SC];
    m[0] = w[0];
#pragma unroll
    for (int i = 1; i < SC-1; i++) m[i] = fmaxf(w[i-1], w[i]);
    m[SC-1] = w[SC-2];

    // importance weights used: w_new[1..45] where w_new[i]=0.5*(m[i]+m[i+1])+0.01
    float pw[45];
    float sum = 0.f;
#pragma unroll
    for (int j = 0; j < 45; j++) {
        float v = 0.5f*(m[j+1] + m[j+2]) + 0.01f + 1e-5f;
        pw[j] = v; sum += v;
    }
    float cdf[46];
    cdf[0] = 0.f;
    for (int j = 0; j < 45; j++) cdf[j+1] = cdf[j] + pw[j]/sum;

    float bins[SC-1];
#pragma unroll
    for (int i = 0; i < SC-1; i++) bins[i] = 0.5f*(d[i] + d[i+1]);

    const float* up = noise_imp + (size_t)ray*SFN;
    float* out = g_depths_f + (size_t)ray*SFN;
    for (int j = 0; j < SFN; j++) {
        float u = up[j];
        int ind = 0;
        for (int t2 = 0; t2 < 46; t2++) ind += (cdf[t2] <= u) ? 1 : 0;  // searchsorted right
        int below = ind - 1; if (below < 0) below = 0;
        int above = ind;     if (above > 45) above = 45;
        float cb = cdf[below], ca = cdf[above];
        float bb = bins[below], ba = bins[above];
        float den = ca - cb; if (den < 1e-5f) den = 1.f;
        out[j] = bb + (u - cb)/den * (ba - bb);
    }
}

// -------- merge, stable sort by depth, final ray march, outputs --------
__global__ void __launch_bounds__(256) k_final(float* __restrict__ out) {
    int warp = (blockIdx.x * blockDim.x + threadIdx.x) >> 5;
    int lane = threadIdx.x & 31;
    int wloc = threadIdx.x >> 5;
    __shared__ float ds[8][96];
    __shared__ float ss[8][96];
    __shared__ int   ordsh[8][96];
    if (warp >= NRAY) return;
    int ray = warp;

    for (int k = lane; k < 96; k += 32) {
        float dv, sv;
        if (k < SC) { dv = g_depths_c[(size_t)ray*SC + k]; sv = g_sigma_c[(size_t)ray*SC + k]; }
        else        { dv = g_depths_f[(size_t)ray*SFN + k - SC]; sv = g_sigma_f[(size_t)ray*SFN + k - SC]; }
        ds[wloc][k] = dv; ss[wloc][k] = sv;
    }
    __syncwarp();

    // stable ascending rank (ties -> lower original index first, matches stable argsort)
    for (int k = lane; k < 96; k += 32) {
        float di = ds[wloc][k];
        int r = 0;
        for (int j = 0; j < 96; j++) {
            float dj = ds[wloc][j];
            r += (dj < di) || (dj == di && j < k);
        }
        ordsh[wloc][r] = k;
    }
    __syncwarp();

    int i0 = ordsh[wloc][0];
    float dprev = ds[wloc][i0], sprev = ss[wloc][i0];
    float cprev = (i0 < SC) ? g_rgb_c[((size_t)ray*SC + i0)*32 + lane]
                            : g_rgb_f[((size_t)ray*SFN + i0 - SC)*32 + lane];
    float T = 1.f, rgbacc = 0.f, dacc = 0.f, wt = 0.f;
    for (int i = 1; i < 96; i++) {
        int ic = ordsh[wloc][i];
        float dcur = ds[wloc][ic], scur = ss[wloc][ic];
        float ccur = (ic < SC) ? g_rgb_c[((size_t)ray*SC + ic)*32 + lane]
                               : g_rgb_f[((size_t)ray*SFN + ic - SC)*32 + lane];
        float delta = dcur - dprev;
        float dens  = softplusf(0.5f*(sprev + scur) - 1.f);
        float alpha = 1.f - expf(-dens*delta);
        float wgt   = alpha * T;
        T *= (1.f - alpha + 1e-10f);
        rgbacc = fmaf(wgt, 0.5f*(cprev + ccur), rgbacc);
        dacc   = fmaf(wgt, 0.5f*(dprev + dcur), dacc);
        wt    += wgt;
        dprev = dcur; sprev = scur; cprev = ccur;
    }

    out[(size_t)ray*32 + lane] = rgbacc*2.f - 1.f;
    if (lane == 0) {
        float depth = dacc / wt;
        if (!isfinite(depth)) depth = dprev;   // NaN->clip-to-max path (practically unreachable)
        out[(size_t)NRAY*32 + ray] = depth;
        out[(size_t)NRAY*33 + ray] = wt;
        out[(size_t)NRAY*34 + ray] = T;        // visibility
    }
}

extern "C" void kernel_launch(void* const* d_in, const int* in_sizes, int n_in,
                              void* d_out, int out_size) {
    const float* planes = (const float*)d_in[0];
    const float* ro     = (const float*)d_in[1];
    const float* rd     = (const float*)d_in[2];
    const float* w1     = (const float*)d_in[3];
    const float* b1     = (const float*)d_in[4];
    const float* w2     = (const float*)d_in[5];
    const float* b2     = (const float*)d_in[6];
    const float* nstrat = (const float*)d_in[7];
    const float* nimp   = (const float*)d_in[8];
    float* out = (float*)d_out;

    k_transpose<<<dim3(RES*RES/32, 1, BB*3), dim3(32, 32)>>>(planes);
    k_coarse_depths<<<(NSAMP + 255)/256, 256>>>(nstrat);
    k_eval<<<NSAMP/128, 128>>>(ro, rd, w1, b1, w2, b2, /*fine=*/0);
    k_importance<<<(NRAY + 127)/128, 128>>>(nimp);
    k_eval<<<NSAMP/128, 128>>>(ro, rd, w1, b1, w2, b2, /*fine=*/1);
    k_final<<<(NRAY*32)/256, 256>>>(out);
}

// round 2
// speedup vs baseline: 1.4172x; 1.4172x over previous
#include <cuda_runtime.h>
#include <math.h>
#include <stdint.h>

// Problem constants
#define BB   2
#define RR   4096
#define SC   48
#define SFN  48
#define CF   32
#define RES  256
#define HID  64
#define ODIM 33          // 1 + OUT_DIM
#define NRAY  (BB*RR)    // 8192
#define NSAMP (NRAY*SC)  // 393216

#define DELTA_F ((2.0f - 0.1f) / (float)(SC - 1))

typedef unsigned long long ull;

// -------- device scratch (no allocations allowed) --------
__device__ float g_planes_t[(size_t)BB*3*RES*RES*CF]; // [b,p,y,x,c]
__device__ float g_depths_c[NSAMP];
__device__ float g_depths_f[NSAMP];
__device__ float g_sigma_c[NSAMP];
__device__ float g_sigma_f[NSAMP];
__device__ float g_rgb_c[(size_t)NSAMP*32];
__device__ float g_rgb_f[(size_t)NSAMP*32];
__device__ float g_w1t[HID*CF];     // [j][i], pre-scaled by 1/3
__device__ float g_w2p[HID*36];     // [j][k], padded 33->36
__device__ float g_b2p[36];

// ---- packed f32x2 helpers (Blackwell FFMA2 via PTX) ----
__device__ __forceinline__ ull pack2(float lo, float hi) {
    ull r; asm("mov.b64 %0, {%1,%2};" : "=l"(r) : "f"(lo), "f"(hi)); return r;
}
__device__ __forceinline__ void unpack2(ull v, float& lo, float& hi) {
    asm("mov.b64 {%0,%1}, %2;" : "=f"(lo), "=f"(hi) : "l"(v));
}
__device__ __forceinline__ ull fma2(ull a, ull b, ull c) {
    ull r; asm("fma.rn.f32x2 %0, %1, %2, %3;" : "=l"(r) : "l"(a), "l"(b), "l"(c)); return r;
}

__device__ __forceinline__ float softplus_fast(float x) {
    // matches jax.nn.softplus = logaddexp(x,0); MUFU-based
    float l = __logf(1.f + __expf(-fabsf(x)));
    return (x > 0.f) ? (x + l) : l;
}

// -------- transpose planes [b,p,c,y,x] -> [b,p,y,x,c] --------
__global__ void k_transpose(const float* __restrict__ in) {
    __shared__ float tile[32][33];
    int bp = blockIdx.z;
    int m0 = blockIdx.x * 32;          // m = y*RES + x
    int tx = threadIdx.x, ty = threadIdx.y;
    tile[ty][tx] = in[((size_t)bp*CF + ty)*(RES*RES) + m0 + tx];
    __syncthreads();
    g_planes_t[((size_t)bp*(RES*RES) + (m0 + ty))*CF + tx] = tile[tx][ty];
}

// -------- weight prep: transpose/scale w1, pad w2, pad b2 --------
__global__ void k_prep(const float* __restrict__ w1, const float* __restrict__ w2,
                       const float* __restrict__ b2) {
    int t = blockIdx.x * blockDim.x + threadIdx.x;
    if (t < HID*CF) {
        int j = t / CF, i = t % CF;
        g_w1t[j*CF + i] = w1[i*HID + j] * (1.f/3.f);   // fold plane-mean /3
    }
    if (t < HID*36) {
        int j = t / 36, k = t % 36;
        g_w2p[j*36 + k] = (k < ODIM) ? w2[j*ODIM + k] : 0.f;
    }
    if (t < 36) g_b2p[t] = (t < ODIM) ? b2[t] : 0.f;
}

// -------- coarse stratified depths --------
__global__ void k_coarse_depths(const float* __restrict__ noise) {
    int i = blockIdx.x * blockDim.x + threadIdx.x;
    if (i >= NSAMP) return;
    int s = i % SC;
    g_depths_c[i] = 0.1f + (float)s * DELTA_F + noise[i] * DELTA_F;
}

// -------- model eval: tri-plane gather + fused 2-layer MLP (f32x2 packed) --------
__global__ void __launch_bounds__(128) k_eval(
    const float* __restrict__ ro, const float* __restrict__ rd,
    const float* __restrict__ b1, int fine)
{
    __shared__ __align__(16) float sw1t[HID*CF];
    __shared__ __align__(16) float sw2p[HID*36];
    __shared__ __align__(16) float sb1[HID];
    __shared__ __align__(16) float sb2p[36];

    int tid = threadIdx.x;
    for (int i = tid; i < HID*CF; i += 128) sw1t[i] = g_w1t[i];
    for (int i = tid; i < HID*36; i += 128) sw2p[i] = g_w2p[i];
    if (tid < HID) sb1[tid] = b1[tid];
    if (tid < 36)  sb2p[tid] = g_b2p[tid];
    __syncthreads();

    int idx = blockIdx.x * 128 + tid;

    const float* depths = fine ? g_depths_f : g_depths_c;
    float* sigma_out    = fine ? g_sigma_f  : g_sigma_c;
    float* rgb_out      = fine ? g_rgb_f    : g_rgb_c;

    int ray = idx / SC;
    int b   = ray / RR;

    float t  = depths[idx];
    float cc[3];
    cc[0] = (ro[ray*3+0] + t*rd[ray*3+0]) * 0.5f;
    cc[1] = (ro[ray*3+1] + t*rd[ray*3+1]) * 0.5f;
    cc[2] = (ro[ray*3+2] + t*rd[ray*3+2]) * 0.5f;

    // gather features, packed accumulate (32 ch = 16 f32x2)
    ull ff[16];
#pragma unroll
    for (int i = 0; i < 16; i++) ff[i] = 0ull;

#pragma unroll
    for (int p = 0; p < 3; p++) {
        float gx = cc[p];
        float gy = cc[(p+1)%3];
        float x = ((gx + 1.f)*(float)RES - 1.f)*0.5f;
        float y = ((gy + 1.f)*(float)RES - 1.f)*0.5f;
        float x0f = floorf(x), y0f = floorf(y);
        float wx1 = x - x0f, wy1 = y - y0f;
        float wx0 = 1.f - wx1, wy0 = 1.f - wy1;
        int x0 = (int)x0f, y0 = (int)y0f;
        const float* base = g_planes_t + ((size_t)(b*3 + p))*((size_t)RES*RES*CF);
#pragma unroll
        for (int cy = 0; cy < 2; cy++) {
            int yy = y0 + cy;
            if (yy < 0 || yy >= RES) continue;
            float wyv = cy ? wy1 : wy0;
#pragma unroll
            for (int cx = 0; cx < 2; cx++) {
                int xx = x0 + cx;
                if (xx < 0 || xx >= RES) continue;
                float w = wyv * (cx ? wx1 : wx0);
                ull wp = pack2(w, w);
                const float4* q = (const float4*)(base + ((size_t)yy*RES + xx)*CF);
#pragma unroll
                for (int j = 0; j < 8; j++) {
                    float4 v = q[j];
                    ff[2*j+0] = fma2(wp, pack2(v.x, v.y), ff[2*j+0]);
                    ff[2*j+1] = fma2(wp, pack2(v.z, v.w), ff[2*j+1]);
                }
            }
        }
    }
    // NOTE: 1/3 mean factor folded into sw1t

    // fused MLP: per hidden unit j compute h_j, immediately accumulate layer 2
    ull o2[18];
    const ull* b2q = (const ull*)sb2p;
#pragma unroll
    for (int k2 = 0; k2 < 18; k2++) o2[k2] = b2q[k2];

    const ull* w1q = (const ull*)sw1t;
    const ull* w2q = (const ull*)sw2p;
#pragma unroll 4
    for (int j = 0; j < HID; j++) {
        ull acc = 0ull;
#pragma unroll
        for (int i2 = 0; i2 < 16; i2++)
            acc = fma2(w1q[j*16 + i2], ff[i2], acc);
        float alo, ahi; unpack2(acc, alo, ahi);
        float hj = softplus_fast(alo + ahi + sb1[j]);
        ull hp = pack2(hj, hj);
#pragma unroll
        for (int k2 = 0; k2 < 18; k2++)
            o2[k2] = fma2(hp, w2q[j*18 + k2], o2[k2]);
    }

    float o[36];
#pragma unroll
    for (int k2 = 0; k2 < 18; k2++) unpack2(o2[k2], o[2*k2], o[2*k2+1]);

    sigma_out[idx] = o[0];
    float4* o4 = (float4*)(rgb_out + (size_t)idx*32);
#pragma unroll
    for (int kk = 0; kk < 8; kk++) {
        float4 v;
        v.x = __fdividef(1.002f, 1.f + __expf(-o[1+4*kk+0])) - 0.001f;
        v.y = __fdividef(1.002f, 1.f + __expf(-o[1+4*kk+1])) - 0.001f;
        v.z = __fdividef(1.002f, 1.f + __expf(-o[1+4*kk+2])) - 0.001f;
        v.w = __fdividef(1.002f, 1.f + __expf(-o[1+4*kk+3])) - 0.001f;
        o4[kk] = v;
    }
}

// -------- warp-per-ray: coarse march weights + inverse-CDF sampling --------
__global__ void __launch_bounds__(128) k_importance(const float* __restrict__ nimp) {
    int gw   = (blockIdx.x * 128 + threadIdx.x) >> 5;
    int lane = threadIdx.x & 31;
    int wl   = threadIdx.x >> 5;
    __shared__ float sh_d[4][48], sh_s[4][48];
    __shared__ float sh_a[4][48];          // alpha, then reused as pw
    __shared__ float sh_w[4][48];          // weights; [47] holds cdf total
    __shared__ float sh_cdf[4][46];
    __shared__ float sh_bins[4][48];
    if (gw >= NRAY) return;

    const float* dp = g_depths_c + (size_t)gw*SC;
    const float* sp = g_sigma_c  + (size_t)gw*SC;
    for (int i = lane; i < 48; i += 32) { sh_d[wl][i] = dp[i]; sh_s[wl][i] = sp[i]; }
    __syncwarp();

    for (int i = lane; i < 47; i += 32) {
        float d0 = sh_d[wl][i], d1 = sh_d[wl][i+1];
        float dens = softplus_fast(0.5f*(sh_s[wl][i] + sh_s[wl][i+1]) - 1.f);
        sh_a[wl][i]    = 1.f - __expf(-dens*(d1 - d0));
        sh_bins[wl][i] = 0.5f*(d0 + d1);
    }
    __syncwarp();

    if (lane == 0) {
        float T = 1.f;
        for (int i = 0; i < 47; i++) {
            float a = sh_a[wl][i];
            sh_w[wl][i] = a * T;
            T *= (1.f - a + 1e-10f);
        }
    }
    __syncwarp();

    // pw[j] = 0.5*(m[j+1]+m[j+2]) + 0.01 + 1e-5, m interior = max(w[i-1],w[i])
    for (int j = lane; j < 45; j += 32) {
        float m1 = fmaxf(sh_w[wl][j],   sh_w[wl][j+1]);
        float m2 = fmaxf(sh_w[wl][j+1], sh_w[wl][j+2]);
        sh_a[wl][j] = 0.5f*(m1 + m2) + 0.01f + 1e-5f;
    }
    __syncwarp();

    if (lane == 0) {
        float c = 0.f;
        sh_cdf[wl][0] = 0.f;
        for (int j = 0; j < 45; j++) { c += sh_a[wl][j]; sh_cdf[wl][j+1] = c; }
        sh_w[wl][47] = c;
    }
    __syncwarp();
    float inv = __fdividef(1.f, sh_w[wl][47]);
    for (int j = lane + 1; j < 46; j += 32) sh_cdf[wl][j] *= inv;
    __syncwarp();

    const float* up = nimp + (size_t)gw*SFN;
    float* outp = g_depths_f + (size_t)gw*SFN;
    for (int j = lane; j < SFN; j += 32) {
        float u = up[j];
        int ind = 0;
#pragma unroll
        for (int t2 = 0; t2 < 46; t2++) ind += (sh_cdf[wl][t2] <= u) ? 1 : 0;
        int below = ind - 1; if (below < 0) below = 0;
        int above = ind;     if (above > 45) above = 45;
        float cb = sh_cdf[wl][below], ca = sh_cdf[wl][above];
        float bb = sh_bins[wl][below], ba = sh_bins[wl][above];
        float den = ca - cb; if (den < 1e-5f) den = 1.f;
        outp[j] = bb + (u - cb)/den * (ba - bb);
    }
}

// -------- merge, stable sort by depth, final ray march, outputs --------
__global__ void __launch_bounds__(256) k_final(float* __restrict__ out) {
    int warp = (blockIdx.x * blockDim.x + threadIdx.x) >> 5;
    int lane = threadIdx.x & 31;
    int wloc = threadIdx.x >> 5;
    __shared__ float ds[8][96];
    __shared__ float ss[8][96];
    __shared__ int   ordsh[8][96];
    if (warp >= NRAY) return;
    int ray = warp;

    for (int k = lane; k < 96; k += 32) {
        float dv, sv;
        if (k < SC) { dv = g_depths_c[(size_t)ray*SC + k]; sv = g_sigma_c[(size_t)ray*SC + k]; }
        else        { dv = g_depths_f[(size_t)ray*SFN + k - SC]; sv = g_sigma_f[(size_t)ray*SFN + k - SC]; }
        ds[wloc][k] = dv; ss[wloc][k] = sv;
    }
    __syncwarp();

    // stable ascending rank (ties -> lower original index first)
    for (int k = lane; k < 96; k += 32) {
        float di = ds[wloc][k];
        int r = 0;
        for (int j = 0; j < 96; j++) {
            float dj = ds[wloc][j];
            r += (dj < di) || (dj == di && j < k);
        }
        ordsh[wloc][r] = k;
    }
    __syncwarp();

    int i0 = ordsh[wloc][0];
    float dprev = ds[wloc][i0], sprev = ss[wloc][i0];
    float cprev = (i0 < SC) ? g_rgb_c[((size_t)ray*SC + i0)*32 + lane]
                            : g_rgb_f[((size_t)ray*SFN + i0 - SC)*32 + lane];
    float T = 1.f, rgbacc = 0.f, dacc = 0.f, wt = 0.f;
    for (int i = 1; i < 96; i++) {
        int ic = ordsh[wloc][i];
        float dcur = ds[wloc][ic], scur = ss[wloc][ic];
        float ccur = (ic < SC) ? g_rgb_c[((size_t)ray*SC + ic)*32 + lane]
                               : g_rgb_f[((size_t)ray*SFN + ic - SC)*32 + lane];
        float delta = dcur - dprev;
        float dens  = softplus_fast(0.5f*(sprev + scur) - 1.f);
        float alpha = 1.f - __expf(-dens*delta);
        float wgt   = alpha * T;
        T *= (1.f - alpha + 1e-10f);
        rgbacc = fmaf(wgt, 0.5f*(cprev + ccur), rgbacc);
        dacc   = fmaf(wgt, 0.5f*(dprev + dcur), dacc);
        wt    += wgt;
        dprev = dcur; sprev = scur; cprev = ccur;
    }

    out[(size_t)ray*32 + lane] = rgbacc*2.f - 1.f;
    if (lane == 0) {
        float depth = dacc / wt;
        if (!isfinite(depth)) depth = dprev;   // NaN path (practically unreachable)
        out[(size_t)NRAY*32 + ray] = depth;
        out[(size_t)NRAY*33 + ray] = wt;
        out[(size_t)NRAY*34 + ray] = T;        // visibility
    }
}

extern "C" void kernel_launch(void* const* d_in, const int* in_sizes, int n_in,
                              void* d_out, int out_size) {
    const float* planes = (const float*)d_in[0];
    const float* ro     = (const float*)d_in[1];
    const float* rd     = (const float*)d_in[2];
    const float* w1     = (const float*)d_in[3];
    const float* b1     = (const float*)d_in[4];
    const float* w2     = (const float*)d_in[5];
    const float* b2     = (const float*)d_in[6];
    const float* nstrat = (const float*)d_in[7];
    const float* nimp   = (const float*)d_in[8];
    float* out = (float*)d_out;

    k_transpose<<<dim3(RES*RES/32, 1, BB*3), dim3(32, 32)>>>(planes);
    k_prep<<<9, 256>>>(w1, w2, b2);
    k_coarse_depths<<<(NSAMP + 255)/256, 256>>>(nstrat);
    k_eval<<<NSAMP/128, 128>>>(ro, rd, b1, /*fine=*/0);
    k_importance<<<(NRAY*32)/128, 128>>>(nimp);
    k_eval<<<NSAMP/128, 128>>>(ro, rd, b1, /*fine=*/1);
    k_final<<<(NRAY*32)/256, 256>>>(out);
}

// round 4
// speedup vs baseline: 1.9637x; 1.3856x over previous
#include <cuda_runtime.h>
#include <cuda_bf16.h>
#include <math.h>
#include <stdint.h>

// Problem constants
#define BB   2
#define RR   4096
#define SC   48
#define SFN  48
#define CF   32
#define RES  256
#define HID  64
#define ODIM 33          // 1 + OUT_DIM
#define NRAY  (BB*RR)    // 8192
#define NSAMP (NRAY*SC)  // 393216

#define DELTA_F ((2.0f - 0.1f) / (float)(SC - 1))

typedef unsigned long long ull;

// ---- packed f32x2 helpers (Blackwell FFMA2 via PTX, base feature) ----
__device__ __forceinline__ ull pack2(float lo, float hi) {
    ull r; asm("mov.b64 %0, {%1,%2};" : "=l"(r) : "f"(lo), "f"(hi)); return r;
}
__device__ __forceinline__ ull fma2(ull a, ull b, ull c) {
    ull r; asm("fma.rn.f32x2 %0, %1, %2, %3;" : "=l"(r) : "l"(a), "l"(b), "l"(c)); return r;
}
__device__ __forceinline__ void unpack2(ull v, float& lo, float& hi) {
    asm("mov.b64 {%0,%1}, %2;" : "=f"(lo), "=f"(hi) : "l"(v));
}

__device__ __forceinline__ float softplus_fast(float x) {
    float l = __logf(1.f + __expf(-fabsf(x)));
    return (x > 0.f) ? (x + l) : l;
}

__device__ __forceinline__ uint32_t smem_u32(const void* p) {
    uint32_t a;
    asm("{ .reg .u64 t; cvta.to.shared.u64 t, %1; cvt.u32.u64 %0, t; }" : "=r"(a) : "l"(p));
    return a;
}

// ---- mma / ldmatrix wrappers (base PTX, compute_80+) ----
__device__ __forceinline__ void ldsm_x4(uint32_t& r0, uint32_t& r1, uint32_t& r2, uint32_t& r3, uint32_t addr) {
    asm volatile("ldmatrix.sync.aligned.m8n8.x4.shared.b16 {%0,%1,%2,%3}, [%4];"
        : "=r"(r0), "=r"(r1), "=r"(r2), "=r"(r3) : "r"(addr));
}
__device__ __forceinline__ void ldsm_x2(uint32_t& r0, uint32_t& r1, uint32_t addr) {
    asm volatile("ldmatrix.sync.aligned.m8n8.x2.shared.b16 {%0,%1}, [%2];"
        : "=r"(r0), "=r"(r1) : "r"(addr));
}
__device__ __forceinline__ void mma16816(float& d0, float& d1, float& d2, float& d3,
                                          uint32_t a0, uint32_t a1, uint32_t a2, uint32_t a3,
                                          uint32_t b0, uint32_t b1) {
    asm volatile("mma.sync.aligned.m16n8k16.row.col.f32.bf16.bf16.f32 "
        "{%0,%1,%2,%3}, {%4,%5,%6,%7}, {%8,%9}, {%0,%1,%2,%3};"
        : "+f"(d0), "+f"(d1), "+f"(d2), "+f"(d3)
        : "r"(a0), "r"(a1), "r"(a2), "r"(a3), "r"(b0), "r"(b1));
}

__device__ __forceinline__ __nv_bfloat16 bf_hi(float x) { return __float2bfloat16_rn(x); }
__device__ __forceinline__ uint32_t packbf(float lo, float hi) {
    __nv_bfloat162 h2; h2.x = __float2bfloat16_rn(lo); h2.y = __float2bfloat16_rn(hi);
    return *(uint32_t*)&h2;
}

// -------- device scratch (no allocations allowed) --------
__device__ float g_planes_t[(size_t)BB*3*RES*RES*CF]; // [b,p,y,x,c]
__device__ float g_depths_c[NSAMP];
__device__ float g_depths_f[NSAMP];
__device__ float g_sigma_c[NSAMP];
__device__ float g_sigma_f[NSAMP];
__device__ float g_rgb_c[(size_t)NSAMP*32];
__device__ float g_rgb_f[(size_t)NSAMP*32];
// B^T weight tiles, row-major [N][K], 256B rows, XOR-chunk swizzled
__device__ uint32_t g_Bt1[64*64];    // 64 rows x 256B = 16KB
__device__ uint32_t g_Bt2[48*64];    // 48 rows x 256B = 12KB

// -------- transpose planes [b,p,c,y,x] -> [b,p,y,x,c] --------
__global__ void k_transpose(const float* __restrict__ in) {
    __shared__ float tile[32][33];
    int bp = blockIdx.z;
    int m0 = blockIdx.x * 32;
    int tx = threadIdx.x, ty = threadIdx.y;
    tile[ty][tx] = in[((size_t)bp*CF + ty)*(RES*RES) + m0 + tx];
    __syncthreads();
    g_planes_t[((size_t)bp*(RES*RES) + (m0 + ty))*CF + tx] = tile[tx][ty];
}

// -------- weight prep: build swizzled B^T tiles (bf16 hi/lo split) --------
// Bt1 [n=0..63][k=0..95]: k<32 -> hi(w1[k][n]/3); 32..63 -> hi(w1[k-32][n]/3)... see mapping:
//   k 0..31  : hi(W[i=k])      (pairs with a_hi)
//   k 32..63 : hi(W[i=k-32])   (pairs with a_lo)
//   k 64..95 : lo(W[i=k-64])   (pairs with a_hi)
// Bt2 [n=0..47][k=0..127]: k<64 -> hi(w2[j=k][n]); k>=64 -> lo(w2[j=k-64][n]); n>=33 zero.
__global__ void k_prep(const float* __restrict__ w1, const float* __restrict__ w2) {
    int t = threadIdx.x;
    for (int i = t; i < 64*64; i += blockDim.x) g_Bt1[i] = 0;
    for (int i = t; i < 48*64; i += blockDim.x) g_Bt2[i] = 0;
    __syncthreads();
    for (int e = t; e < 64*96; e += blockDim.x) {
        int n = e / 96, k = e % 96;
        int i = k & 31;
        float v = w1[i*HID + n] * (1.f/3.f);
        float hv = __bfloat162float(bf_hi(v));
        __nv_bfloat16 bv = (k < 64) ? bf_hi(v) : bf_hi(v - hv);
        uint32_t pos = (uint32_t)n*256u + ((((uint32_t)k >> 3) ^ (n & 7)) << 4) + (k & 7)*2u;
        *(__nv_bfloat16*)((char*)g_Bt1 + pos) = bv;
    }
    for (int e = t; e < 33*128; e += blockDim.x) {
        int n = e / 128, k = e % 128;
        int j = k & 63;
        float v = w2[j*ODIM + n];
        float hv = __bfloat162float(bf_hi(v));
        __nv_bfloat16 bv = (k < 64) ? bf_hi(v) : bf_hi(v - hv);
        uint32_t pos = (uint32_t)n*256u + ((((uint32_t)k >> 3) ^ (n & 7)) << 4) + (k & 7)*2u;
        *(__nv_bfloat16*)((char*)g_Bt2 + pos) = bv;
    }
}

// -------- coarse stratified depths --------
__global__ void k_coarse_depths(const float* __restrict__ noise) {
    int i = blockIdx.x * blockDim.x + threadIdx.x;
    if (i >= NSAMP) return;
    int s = i % SC;
    g_depths_c[i] = 0.1f + (float)s * DELTA_F + noise[i] * DELTA_F;
}

// -------- tensor-core (mma.sync) model eval --------
// Block = 128 threads = 4 warps = 128 samples. Warp w owns rows 32w..32w+31 (2 M-tiles).
__global__ void __launch_bounds__(128) k_eval_m(
    const float* __restrict__ ro, const float* __restrict__ rd,
    const float* __restrict__ b1, const float* __restrict__ b2, int fine)
{
    __shared__ __align__(16) char sA[128*128];    // 16KB: [128 rows][64 bf16], swizzled
    __shared__ __align__(16) char sB1[64*256];    // 16KB
    __shared__ __align__(16) char sB2[48*256];    // 12KB
    __shared__ float sb1[HID];
    __shared__ float sb2p[48];

    int tid = threadIdx.x;
    {
        uint4* d1 = (uint4*)sB1; const uint4* s1 = (const uint4*)g_Bt1;
        for (int i = tid; i < 1024; i += 128) d1[i] = s1[i];
        uint4* d2 = (uint4*)sB2; const uint4* s2 = (const uint4*)g_Bt2;
        for (int i = tid; i < 768; i += 128) d2[i] = s2[i];
    }
    if (tid < HID) sb1[tid] = b1[tid];
    if (tid < 48)  sb2p[tid] = (tid < ODIM) ? b2[tid] : 0.f;

    int idx = blockIdx.x * 128 + tid;
    const float* depths = fine ? g_depths_f : g_depths_c;
    float* sigma_out    = fine ? g_sigma_f  : g_sigma_c;
    float* rgb_out      = fine ? g_rgb_f    : g_rgb_c;

    int ray = idx / SC;
    int b   = ray / RR;

    float t = depths[idx];
    float cc[3];
    cc[0] = (ro[ray*3+0] + t*rd[ray*3+0]) * 0.5f;
    cc[1] = (ro[ray*3+1] + t*rd[ray*3+1]) * 0.5f;
    cc[2] = (ro[ray*3+2] + t*rd[ray*3+2]) * 0.5f;

    // gather features (packed f32x2 accumulate); 1/3 mean folded into W1
    ull ff[16];
#pragma unroll
    for (int i = 0; i < 16; i++) ff[i] = 0ull;
#pragma unroll
    for (int p = 0; p < 3; p++) {
        float gx = cc[p];
        float gy = cc[(p+1)%3];
        float x = ((gx + 1.f)*(float)RES - 1.f)*0.5f;
        float y = ((gy + 1.f)*(float)RES - 1.f)*0.5f;
        float x0f = floorf(x), y0f = floorf(y);
        float wx1 = x - x0f, wy1 = y - y0f;
        float wx0 = 1.f - wx1, wy0 = 1.f - wy1;
        int x0 = (int)x0f, y0 = (int)y0f;
        const float* base = g_planes_t + ((size_t)(b*3 + p))*((size_t)RES*RES*CF);
#pragma unroll
        for (int cy = 0; cy < 2; cy++) {
            int yy = y0 + cy;
            if (yy < 0 || yy >= RES) continue;
            float wyv = cy ? wy1 : wy0;
#pragma unroll
            for (int cx = 0; cx < 2; cx++) {
                int xx = x0 + cx;
                if (xx < 0 || xx >= RES) continue;
                float w = wyv * (cx ? wx1 : wx0);
                ull wp = pack2(w, w);
                const float4* q = (const float4*)(base + ((size_t)yy*RES + xx)*CF);
#pragma unroll
                for (int j = 0; j < 8; j++) {
                    float4 v = q[j];
                    ff[2*j+0] = fma2(wp, pack2(v.x, v.y), ff[2*j+0]);
                    ff[2*j+1] = fma2(wp, pack2(v.z, v.w), ff[2*j+1]);
                }
            }
        }
    }

    // stage features: row tid, cols 0..31 = hi, 32..63 = lo; 128B rows, XOR-chunk swizzle
    {
        uint32_t rowbase = (uint32_t)tid * 128u;
        uint32_t sw = (tid & 7);
#pragma unroll
        for (int c = 0; c < 16; c++) {
            float f0, f1; unpack2(ff[c], f0, f1);
            float h0 = __bfloat162float(bf_hi(f0));
            float h1 = __bfloat162float(bf_hi(f1));
            uint32_t hiw = packbf(f0, f1);
            uint32_t low = packbf(f0 - h0, f1 - h1);
            // hi: byte col 4c -> chunk c/4, byte-in-chunk (c%4)*4
            uint32_t ph = rowbase + ((((uint32_t)c >> 2) ^ sw) << 4) + (c & 3)*4u;
            // lo: byte col 64+4c -> chunk 4 + c/4
            uint32_t pl = rowbase + (((4u + ((uint32_t)c >> 2)) ^ sw) << 4) + (c & 3)*4u;
            *(uint32_t*)(sA + ph) = hiw;
            *(uint32_t*)(sA + pl) = low;
        }
    }
    __syncthreads();

    uint32_t aBase  = smem_u32(sA);
    uint32_t b1Base = smem_u32(sB1);
    uint32_t b2Base = smem_u32(sB2);

    int wid = tid >> 5, l = tid & 31;
    int lq = l >> 2;            // l/4
    int lr2 = (l & 3) * 2;      // (l%4)*2

    const int ktA_map[6] = {0, 1, 2, 3, 0, 1};

#pragma unroll
    for (int m = 0; m < 2; m++) {
        int R = wid*32 + m*16;

        // A1 fragments (4 k-tiles over the 64 staged cols)
        uint32_t af[4][4];
        {
            int arow = R + (l & 7) + 8*((l >> 3) & 1);
            uint32_t aseg = (uint32_t)(l >> 4);
            uint32_t rb = (uint32_t)arow * 128u;
            uint32_t sw = (uint32_t)(arow & 7);
#pragma unroll
            for (int kt = 0; kt < 4; kt++) {
                uint32_t addr = aBase + rb + ((((uint32_t)kt*2u + aseg) ^ sw) << 4);
                ldsm_x4(af[kt][0], af[kt][1], af[kt][2], af[kt][3], addr);
            }
        }

        // layer 1: for each n-tile accumulate K=96, then softplus+split into A2 frags
        uint32_t a2f[8][4];
        int bl = l & 7;
        uint32_t bseg = (uint32_t)((l >> 3) & 1);
#pragma unroll
        for (int nt = 0; nt < 8; nt++) {
            float d0 = 0.f, d1 = 0.f, d2 = 0.f, d3 = 0.f;
            int bn = nt*8 + bl;
            uint32_t brb = (uint32_t)bn * 256u;
            uint32_t bsw = (uint32_t)(bn & 7);
#pragma unroll
            for (int ks = 0; ks < 6; ks++) {
                uint32_t baddr = b1Base + brb + ((((uint32_t)ks*2u + bseg) ^ bsw) << 4);
                uint32_t bb0, bb1;
                ldsm_x2(bb0, bb1, baddr);
                const uint32_t* a = af[ktA_map[ks]];
                mma16816(d0, d1, d2, d3, a[0], a[1], a[2], a[3], bb0, bb1);
            }
            int col0 = nt*8 + lr2;
            float s0 = softplus_fast(d0 + sb1[col0]);
            float s1 = softplus_fast(d1 + sb1[col0+1]);
            float s2 = softplus_fast(d2 + sb1[col0]);
            float s3 = softplus_fast(d3 + sb1[col0+1]);
            float h0 = __bfloat162float(bf_hi(s0));
            float h1 = __bfloat162float(bf_hi(s1));
            float h2 = __bfloat162float(bf_hi(s2));
            float h3 = __bfloat162float(bf_hi(s3));
            int kk = nt >> 1, half = nt & 1;
            a2f[kk][2*half+0]   = packbf(s0, s1);
            a2f[kk][2*half+1]   = packbf(s2, s3);
            a2f[4+kk][2*half+0] = packbf(s0 - h0, s1 - h1);
            a2f[4+kk][2*half+1] = packbf(s2 - h2, s3 - h3);
        }

        // layer 2: N=48 (6 n-tiles), K=128 (8 k-tiles)
#pragma unroll
        for (int nt2 = 0; nt2 < 6; nt2++) {
            float e0 = 0.f, e1 = 0.f, e2 = 0.f, e3 = 0.f;
            int bn = nt2*8 + bl;
            uint32_t brb = (uint32_t)bn * 256u;
            uint32_t bsw = (uint32_t)(bn & 7);
#pragma unroll
            for (int kk = 0; kk < 8; kk++) {
                uint32_t baddr = b2Base + brb + ((((uint32_t)kk*2u + bseg) ^ bsw) << 4);
                uint32_t bb0, bb1;
                ldsm_x2(bb0, bb1, baddr);
                mma16816(e0, e1, e2, e3, a2f[kk][0], a2f[kk][1], a2f[kk][2], a2f[kk][3], bb0, bb1);
            }
            int col0 = nt2*8 + lr2;
            int r0 = blockIdx.x*128 + R + lq;
            int r1 = r0 + 8;
            float vv[4] = {e0, e1, e2, e3};
            int   rr[4] = {r0, r0, r1, r1};
            int   ccl[4] = {col0, col0+1, col0, col0+1};
#pragma unroll
            for (int q = 0; q < 4; q++) {
                int c = ccl[q];
                if (c == 0) {
                    sigma_out[rr[q]] = vv[q] + sb2p[0];
                } else if (c <= 32) {
                    float ov = vv[q] + sb2p[c];
                    rgb_out[(size_t)rr[q]*32 + (c-1)] =
                        __fdividef(1.002f, 1.f + __expf(-ov)) - 0.001f;
                }
            }
        }
    }
}

// -------- warp-per-ray: coarse march weights + inverse-CDF sampling --------
__global__ void __launch_bounds__(128) k_importance(const float* __restrict__ nimp) {
    int gw   = (blockIdx.x * 128 + threadIdx.x) >> 5;
    int lane = threadIdx.x & 31;
    int wl   = threadIdx.x >> 5;
    __shared__ float sh_d[4][48], sh_s[4][48];
    __shared__ float sh_a[4][48];
    __shared__ float sh_w[4][48];
    __shared__ float sh_cdf[4][46];
    __shared__ float sh_bins[4][48];
    if (gw >= NRAY) return;

    const float* dp = g_depths_c + (size_t)gw*SC;
    const float* sp = g_sigma_c  + (size_t)gw*SC;
    for (int i = lane; i < 48; i += 32) { sh_d[wl][i] = dp[i]; sh_s[wl][i] = sp[i]; }
    __syncwarp();

    for (int i = lane; i < 47; i += 32) {
        float d0 = sh_d[wl][i], d1 = sh_d[wl][i+1];
        float dens = softplus_fast(0.5f*(sh_s[wl][i] + sh_s[wl][i+1]) - 1.f);
        sh_a[wl][i]    = 1.f - __expf(-dens*(d1 - d0));
        sh_bins[wl][i] = 0.5f*(d0 + d1);
    }
    __syncwarp();

    if (lane == 0) {
        float T = 1.f;
        for (int i = 0; i < 47; i++) {
            float a = sh_a[wl][i];
            sh_w[wl][i] = a * T;
            T *= (1.f - a + 1e-10f);
        }
    }
    __syncwarp();

    for (int j = lane; j < 45; j += 32) {
        float m1 = fmaxf(sh_w[wl][j],   sh_w[wl][j+1]);
        float m2 = fmaxf(sh_w[wl][j+1], sh_w[wl][j+2]);
        sh_a[wl][j] = 0.5f*(m1 + m2) + 0.01f + 1e-5f;
    }
    __syncwarp();

    if (lane == 0) {
        float c = 0.f;
        sh_cdf[wl][0] = 0.f;
        for (int j = 0; j < 45; j++) { c += sh_a[wl][j]; sh_cdf[wl][j+1] = c; }
        sh_w[wl][47] = c;
    }
    __syncwarp();
    float inv = __fdividef(1.f, sh_w[wl][47]);
    for (int j = lane + 1; j < 46; j += 32) sh_cdf[wl][j] *= inv;
    __syncwarp();

    const float* up = nimp + (size_t)gw*SFN;
    float* outp = g_depths_f + (size_t)gw*SFN;
    for (int j = lane; j < SFN; j += 32) {
        float u = up[j];
        int ind = 0;
#pragma unroll
        for (int t2 = 0; t2 < 46; t2++) ind += (sh_cdf[wl][t2] <= u) ? 1 : 0;
        int below = ind - 1; if (below < 0) below = 0;
        int above = ind;     if (above > 45) above = 45;
        float cb = sh_cdf[wl][below], ca = sh_cdf[wl][above];
        float bb = sh_bins[wl][below], ba = sh_bins[wl][above];
        float den = ca - cb; if (den < 1e-5f) den = 1.f;
        outp[j] = bb + (u - cb)/den * (ba - bb);
    }
}

// -------- merge, stable sort by depth, final ray march, outputs --------
__global__ void __launch_bounds__(256) k_final(float* __restrict__ out) {
    int warp = (blockIdx.x * blockDim.x + threadIdx.x) >> 5;
    int lane = threadIdx.x & 31;
    int wloc = threadIdx.x >> 5;
    __shared__ float ds[8][96];
    __shared__ float ss[8][96];
    __shared__ int   ordsh[8][96];
    if (warp >= NRAY) return;
    int ray = warp;

    for (int k = lane; k < 96; k += 32) {
        float dv, sv;
        if (k < SC) { dv = g_depths_c[(size_t)ray*SC + k]; sv = g_sigma_c[(size_t)ray*SC + k]; }
        else        { dv = g_depths_f[(size_t)ray*SFN + k - SC]; sv = g_sigma_f[(size_t)ray*SFN + k - SC]; }
        ds[wloc][k] = dv; ss[wloc][k] = sv;
    }
    __syncwarp();

    for (int k = lane; k < 96; k += 32) {
        float di = ds[wloc][k];
        int r = 0;
        for (int j = 0; j < 96; j++) {
            float dj = ds[wloc][j];
            r += (dj < di) || (dj == di && j < k);
        }
        ordsh[wloc][r] = k;
    }
    __syncwarp();

    int i0 = ordsh[wloc][0];
    float dprev = ds[wloc][i0], sprev = ss[wloc][i0];
    float cprev = (i0 < SC) ? g_rgb_c[((size_t)ray*SC + i0)*32 + lane]
                            : g_rgb_f[((size_t)ray*SFN + i0 - SC)*32 + lane];
    float T = 1.f, rgbacc = 0.f, dacc = 0.f, wt = 0.f;
    for (int i = 1; i < 96; i++) {
        int ic = ordsh[wloc][i];
        float dcur = ds[wloc][ic], scur = ss[wloc][ic];
        float ccur = (ic < SC) ? g_rgb_c[((size_t)ray*SC + ic)*32 + lane]
                               : g_rgb_f[((size_t)ray*SFN + ic - SC)*32 + lane];
        float delta = dcur - dprev;
        float dens  = softplus_fast(0.5f*(sprev + scur) - 1.f);
        float alpha = 1.f - __expf(-dens*delta);
        float wgt   = alpha * T;
        T *= (1.f - alpha + 1e-10f);
        rgbacc = fmaf(wgt, 0.5f*(cprev + ccur), rgbacc);
        dacc   = fmaf(wgt, 0.5f*(dprev + dcur), dacc);
        wt    += wgt;
        dprev = dcur; sprev = scur; cprev = ccur;
    }

    out[(size_t)ray*32 + lane] = rgbacc*2.f - 1.f;
    if (lane == 0) {
        float depth = dacc / wt;
        if (!isfinite(depth)) depth = dprev;
        out[(size_t)NRAY*32 + ray] = depth;
        out[(size_t)NRAY*33 + ray] = wt;
        out[(size_t)NRAY*34 + ray] = T;
    }
}

extern "C" void kernel_launch(void* const* d_in, const int* in_sizes, int n_in,
                              void* d_out, int out_size) {
    const float* planes = (const float*)d_in[0];
    const float* ro     = (const float*)d_in[1];
    const float* rd     = (const float*)d_in[2];
    const float* w1     = (const float*)d_in[3];
    const float* b1     = (const float*)d_in[4];
    const float* w2     = (const float*)d_in[5];
    const float* b2     = (const float*)d_in[6];
    const float* nstrat = (const float*)d_in[7];
    const float* nimp   = (const float*)d_in[8];
    float* out = (float*)d_out;

    k_transpose<<<dim3(RES*RES/32, 1, BB*3), dim3(32, 32)>>>(planes);
    k_prep<<<1, 512>>>(w1, w2);
    k_coarse_depths<<<(NSAMP + 255)/256, 256>>>(nstrat);
    k_eval_m<<<NSAMP/128, 128>>>(ro, rd, b1, b2, /*fine=*/0);
    k_importance<<<(NRAY*32)/128, 128>>>(nimp);
    k_eval_m<<<NSAMP/128, 128>>>(ro, rd, b1, b2, /*fine=*/1);
    k_final<<<(NRAY*32)/256, 256>>>(out);
}

// round 5
// speedup vs baseline: 2.0357x; 1.0367x over previous
#include <cuda_runtime.h>
#include <cuda_bf16.h>
#include <math.h>
#include <stdint.h>

// Problem constants
#define BB   2
#define RR   4096
#define SC   48
#define SFN  48
#define CF   32
#define RES  256
#define HID  64
#define ODIM 33          // 1 + OUT_DIM
#define NRAY  (BB*RR)    // 8192
#define NSAMP (NRAY*SC)  // 393216

#define DELTA_F ((2.0f - 0.1f) / (float)(SC - 1))

typedef unsigned long long ull;

// ---- packed f32x2 helpers ----
__device__ __forceinline__ ull pack2(float lo, float hi) {
    ull r; asm("mov.b64 %0, {%1,%2};" : "=l"(r) : "f"(lo), "f"(hi)); return r;
}
__device__ __forceinline__ ull fma2(ull a, ull b, ull c) {
    ull r; asm("fma.rn.f32x2 %0, %1, %2, %3;" : "=l"(r) : "l"(a), "l"(b), "l"(c)); return r;
}
__device__ __forceinline__ void unpack2(ull v, float& lo, float& hi) {
    asm("mov.b64 {%0,%1}, %2;" : "=f"(lo), "=f"(hi) : "l"(v));
}

__device__ __forceinline__ float softplus_fast(float x) {
    float l = __logf(1.f + __expf(-fabsf(x)));
    return (x > 0.f) ? (x + l) : l;
}

__device__ __forceinline__ uint32_t smem_u32(const void* p) {
    uint32_t a;
    asm("{ .reg .u64 t; cvta.to.shared.u64 t, %1; cvt.u32.u64 %0, t; }" : "=r"(a) : "l"(p));
    return a;
}

// ---- mma / ldmatrix wrappers (base PTX, compute_80+) ----
__device__ __forceinline__ void ldsm_x4(uint32_t& r0, uint32_t& r1, uint32_t& r2, uint32_t& r3, uint32_t addr) {
    asm volatile("ldmatrix.sync.aligned.m8n8.x4.shared.b16 {%0,%1,%2,%3}, [%4];"
        : "=r"(r0), "=r"(r1), "=r"(r2), "=r"(r3) : "r"(addr));
}
__device__ __forceinline__ void mma16816(float& d0, float& d1, float& d2, float& d3,
                                          uint32_t a0, uint32_t a1, uint32_t a2, uint32_t a3,
                                          uint32_t b0, uint32_t b1) {
    asm volatile("mma.sync.aligned.m16n8k16.row.col.f32.bf16.bf16.f32 "
        "{%0,%1,%2,%3}, {%4,%5,%6,%7}, {%8,%9}, {%0,%1,%2,%3};"
        : "+f"(d0), "+f"(d1), "+f"(d2), "+f"(d3)
        : "r"(a0), "r"(a1), "r"(a2), "r"(a3), "r"(b0), "r"(b1));
}

__device__ __forceinline__ __nv_bfloat16 bf_hi(float x) { return __float2bfloat16_rn(x); }
__device__ __forceinline__ uint32_t packbf(float lo, float hi) {
    __nv_bfloat162 h2; h2.x = __float2bfloat16_rn(lo); h2.y = __float2bfloat16_rn(hi);
    return *(uint32_t*)&h2;
}

// -------- device scratch --------
__device__ float g_planes_t[(size_t)BB*3*RES*RES*CF]; // [b,p,y,x,c]
__device__ float g_depths_c[NSAMP];
__device__ float g_depths_f[NSAMP];
__device__ float g_sigma_c[NSAMP];
__device__ float g_sigma_f[NSAMP];
__device__ float g_rgb_c[(size_t)NSAMP*32];
__device__ float g_rgb_f[(size_t)NSAMP*32];
// B^T weight tiles, swizzled:
// Bt1: [64 n][64 bf16] rows 128B: cols 0..31 = hi(W1/3), 32..63 = lo(W1/3)
__device__ uint32_t g_Bt1[64*32];    // 8KB
// Bt2: [40 n][128 bf16] rows 256B: cols 0..63 = hi(W2perm), 64..127 = lo(W2perm)
//      output permutation: row n<32 -> out n+1 (rgb n), n==32 -> out 0 (sigma), n>32 zero
__device__ uint32_t g_Bt2[40*64];    // 10KB

// -------- transpose planes [b,p,c,y,x] -> [b,p,y,x,c] --------
__global__ void k_transpose(const float* __restrict__ in) {
    __shared__ float tile[32][33];
    int bp = blockIdx.z;
    int m0 = blockIdx.x * 32;
    int tx = threadIdx.x, ty = threadIdx.y;
    tile[ty][tx] = in[((size_t)bp*CF + ty)*(RES*RES) + m0 + tx];
    __syncthreads();
    g_planes_t[((size_t)bp*(RES*RES) + (m0 + ty))*CF + tx] = tile[tx][ty];
}

// -------- weight prep --------
__global__ void k_prep(const float* __restrict__ w1, const float* __restrict__ w2) {
    int t = threadIdx.x;
    for (int i = t; i < 64*32; i += blockDim.x) g_Bt1[i] = 0;
    for (int i = t; i < 40*64; i += blockDim.x) g_Bt2[i] = 0;
    __syncthreads();
    // Bt1
    for (int e = t; e < 64*64; e += blockDim.x) {
        int n = e >> 6, k = e & 63;
        int i = k & 31;
        float v = w1[i*HID + n] * (1.f/3.f);
        float hv = __bfloat162float(bf_hi(v));
        __nv_bfloat16 bv = (k < 32) ? bf_hi(v) : bf_hi(v - hv);
        uint32_t pos = (uint32_t)n*128u + ((((uint32_t)k >> 3) ^ (n & 7)) << 4) + (k & 7)*2u;
        *(__nv_bfloat16*)((char*)g_Bt1 + pos) = bv;
    }
    // Bt2 (rows 0..32 real; 33..39 stay zero)
    for (int e = t; e < 33*128; e += blockDim.x) {
        int n = e >> 7, k = e & 127;
        int out = (n < 32) ? (n + 1) : 0;
        int j = k & 63;
        float v = w2[j*ODIM + out];
        float hv = __bfloat162float(bf_hi(v));
        __nv_bfloat16 bv = (k < 64) ? bf_hi(v) : bf_hi(v - hv);
        uint32_t pos = (uint32_t)n*256u + ((((uint32_t)k >> 3) ^ (n & 7)) << 4) + (k & 7)*2u;
        *(__nv_bfloat16*)((char*)g_Bt2 + pos) = bv;
    }
}

// -------- coarse stratified depths --------
__global__ void k_coarse_depths(const float* __restrict__ noise) {
    int i = blockIdx.x * blockDim.x + threadIdx.x;
    if (i >= NSAMP) return;
    int s = i % SC;
    g_depths_c[i] = 0.1f + (float)s * DELTA_F + noise[i] * DELTA_F;
}

// -------- tensor-core (mma.sync) model eval --------
__global__ void __launch_bounds__(128, 4) k_eval_m(
    const float* __restrict__ ro, const float* __restrict__ rd,
    const float* __restrict__ b1, const float* __restrict__ b2, int fine)
{
    __shared__ __align__(16) char sA[128*128];    // 16KB
    __shared__ __align__(16) char sB1[64*128];    // 8KB
    __shared__ __align__(16) char sB2[40*256];    // 10KB
    __shared__ float sb1[HID];
    __shared__ float sb2p[40];

    int tid = threadIdx.x;
    {
        uint4* d1 = (uint4*)sB1; const uint4* s1 = (const uint4*)g_Bt1;
        for (int i = tid; i < 512; i += 128) d1[i] = s1[i];
        uint4* d2 = (uint4*)sB2; const uint4* s2 = (const uint4*)g_Bt2;
        for (int i = tid; i < 640; i += 128) d2[i] = s2[i];
    }
    if (tid < HID) sb1[tid] = b1[tid];
    if (tid < 40)  sb2p[tid] = (tid < 32) ? b2[tid + 1] : ((tid == 32) ? b2[0] : 0.f);

    int idx = blockIdx.x * 128 + tid;
    const float* depths = fine ? g_depths_f : g_depths_c;
    float* sigma_out    = fine ? g_sigma_f  : g_sigma_c;
    float* rgb_out      = fine ? g_rgb_f    : g_rgb_c;

    int ray = idx / SC;
    int b   = ray / RR;

    float t = depths[idx];
    float cc[3];
    cc[0] = (ro[ray*3+0] + t*rd[ray*3+0]) * 0.5f;
    cc[1] = (ro[ray*3+1] + t*rd[ray*3+1]) * 0.5f;
    cc[2] = (ro[ray*3+2] + t*rd[ray*3+2]) * 0.5f;

    // gather features (packed f32x2); 1/3 mean folded into W1
    ull ff[16];
#pragma unroll
    for (int i = 0; i < 16; i++) ff[i] = 0ull;
#pragma unroll
    for (int p = 0; p < 3; p++) {
        float gx = cc[p];
        float gy = cc[(p+1)%3];
        float x = ((gx + 1.f)*(float)RES - 1.f)*0.5f;
        float y = ((gy + 1.f)*(float)RES - 1.f)*0.5f;
        float x0f = floorf(x), y0f = floorf(y);
        float wx1 = x - x0f, wy1 = y - y0f;
        float wx0 = 1.f - wx1, wy0 = 1.f - wy1;
        int x0 = (int)x0f, y0 = (int)y0f;
        const float* base = g_planes_t + ((size_t)(b*3 + p))*((size_t)RES*RES*CF);
#pragma unroll
        for (int cy = 0; cy < 2; cy++) {
            int yy = y0 + cy;
            if (yy < 0 || yy >= RES) continue;
            float wyv = cy ? wy1 : wy0;
#pragma unroll
            for (int cx = 0; cx < 2; cx++) {
                int xx = x0 + cx;
                if (xx < 0 || xx >= RES) continue;
                float w = wyv * (cx ? wx1 : wx0);
                ull wp = pack2(w, w);
                const float4* q = (const float4*)(base + ((size_t)yy*RES + xx)*CF);
#pragma unroll
                for (int j = 0; j < 8; j++) {
                    float4 v = q[j];
                    ff[2*j+0] = fma2(wp, pack2(v.x, v.y), ff[2*j+0]);
                    ff[2*j+1] = fma2(wp, pack2(v.z, v.w), ff[2*j+1]);
                }
            }
        }
    }

    // stage features: row tid, cols 0..31 hi, 32..63 lo; 128B rows, XOR swizzle
    {
        uint32_t rowbase = (uint32_t)tid * 128u;
        uint32_t sw = (tid & 7);
#pragma unroll
        for (int c = 0; c < 16; c++) {
            float f0, f1; unpack2(ff[c], f0, f1);
            float h0 = __bfloat162float(bf_hi(f0));
            float h1 = __bfloat162float(bf_hi(f1));
            uint32_t hiw = packbf(f0, f1);
            uint32_t low = packbf(f0 - h0, f1 - h1);
            uint32_t ph = rowbase + ((((uint32_t)c >> 2) ^ sw) << 4) + (c & 3)*4u;
            uint32_t pl = rowbase + (((4u + ((uint32_t)c >> 2)) ^ sw) << 4) + (c & 3)*4u;
            *(uint32_t*)(sA + ph) = hiw;
            *(uint32_t*)(sA + pl) = low;
        }
    }
    __syncthreads();

    uint32_t aBase  = smem_u32(sA);
    uint32_t b1Base = smem_u32(sB1);
    uint32_t b2Base = smem_u32(sB2);

    int wid = tid >> 5, l = tid & 31;
    int lq = l >> 2;            // row in fragment
    int lr2 = (l & 3) * 2;      // col pair base

#pragma unroll
    for (int m = 0; m < 2; m++) {
        int R = wid*32 + m*16;

        // A1 fragments: 4 k-tiles over staged 64 cols
        uint32_t af[4][4];
        {
            int arow = R + (l & 7) + 8*((l >> 3) & 1);
            uint32_t aseg = (uint32_t)(l >> 4);
            uint32_t rb = (uint32_t)arow * 128u;
            uint32_t sw = (uint32_t)(arow & 7);
#pragma unroll
            for (int kt = 0; kt < 4; kt++) {
                uint32_t addr = aBase + rb + ((((uint32_t)kt*2u + aseg) ^ sw) << 4);
                ldsm_x4(af[kt][0], af[kt][1], af[kt][2], af[kt][3], addr);
            }
        }

        // ---- layer 1: K=96 = a_hi*Whi + a_lo*Whi + a_hi*Wlo ----
        uint32_t a2f[8][4];
        {
            int brow = (l & 7);
            uint32_t bchunk = (uint32_t)(l >> 3);   // 0..3
#pragma unroll
            for (int nt = 0; nt < 8; nt++) {
                int bn = nt*8 + brow;
                uint32_t brb = (uint32_t)bn * 128u;
                uint32_t bsw = (uint32_t)(bn & 7);
                uint32_t hA0, hA1, hB0, hB1, lA0, lA1, lB0, lB1;
                ldsm_x4(hA0, hA1, hB0, hB1, b1Base + brb + ((bchunk ^ bsw) << 4));          // Whi chunks 0..3
                ldsm_x4(lA0, lA1, lB0, lB1, b1Base + brb + (((4u + bchunk) ^ bsw) << 4));   // Wlo chunks 4..7
                float d0 = 0.f, d1 = 0.f, d2 = 0.f, d3 = 0.f;
                mma16816(d0,d1,d2,d3, af[0][0],af[0][1],af[0][2],af[0][3], hA0,hA1); // a_hi k0 * Whi
                mma16816(d0,d1,d2,d3, af[1][0],af[1][1],af[1][2],af[1][3], hB0,hB1); // a_hi k1 * Whi
                mma16816(d0,d1,d2,d3, af[2][0],af[2][1],af[2][2],af[2][3], hA0,hA1); // a_lo k0 * Whi
                mma16816(d0,d1,d2,d3, af[3][0],af[3][1],af[3][2],af[3][3], hB0,hB1); // a_lo k1 * Whi
                mma16816(d0,d1,d2,d3, af[0][0],af[0][1],af[0][2],af[0][3], lA0,lA1); // a_hi k0 * Wlo
                mma16816(d0,d1,d2,d3, af[1][0],af[1][1],af[1][2],af[1][3], lB0,lB1); // a_hi k1 * Wlo

                int col0 = nt*8 + lr2;
                float s0 = softplus_fast(d0 + sb1[col0]);
                float s1 = softplus_fast(d1 + sb1[col0+1]);
                float s2 = softplus_fast(d2 + sb1[col0]);
                float s3 = softplus_fast(d3 + sb1[col0+1]);
                float h0 = __bfloat162float(bf_hi(s0));
                float h1 = __bfloat162float(bf_hi(s1));
                float h2 = __bfloat162float(bf_hi(s2));
                float h3 = __bfloat162float(bf_hi(s3));
                int kk = nt >> 1, half = nt & 1;
                a2f[kk][2*half+0]   = packbf(s0, s1);
                a2f[kk][2*half+1]   = packbf(s2, s3);
                a2f[4+kk][2*half+0] = packbf(s0 - h0, s1 - h1);
                a2f[4+kk][2*half+1] = packbf(s2 - h2, s3 - h3);
            }
        }

        // ---- layer 2: K=192 = h_hi*Whi + h_lo*Whi + h_hi*Wlo ; N=40 (permuted cols) ----
        {
            int brow = (l & 7);
            uint32_t bchunk = (uint32_t)(l >> 3);   // 0..3
            int r0 = blockIdx.x*128 + R + lq;
            int r1 = r0 + 8;
#pragma unroll
            for (int nt2 = 0; nt2 < 5; nt2++) {
                int bn = nt2*8 + brow;
                uint32_t brb = (uint32_t)bn * 256u;
                uint32_t bsw = (uint32_t)(bn & 7);
                uint32_t e0r[4], e1r[4], f0r[4], f1r[4];
                // Whi chunks 0..7 (k-tiles 0..3), Wlo chunks 8..15 (k-tiles 4..7)
                ldsm_x4(e0r[0], e0r[1], e0r[2], e0r[3], b2Base + brb + (((bchunk     ) ^ bsw) << 4));
                ldsm_x4(e1r[0], e1r[1], e1r[2], e1r[3], b2Base + brb + ((((4u+bchunk) ^ bsw) | 0u) << 4) + 0u*0u + ((4u+bchunk)>=8u ? 0u:0u));
                // NOTE: chunks 4..7: value (4+bchunk) in [4,7] -> XOR bsw stays in [0,7]
                ldsm_x4(f0r[0], f0r[1], f0r[2], f0r[3], b2Base + brb + ((8u + ((bchunk    ) ^ bsw)) << 4));
                ldsm_x4(f1r[0], f1r[1], f1r[2], f1r[3], b2Base + brb + ((8u + (((4u+bchunk) ^ bsw) & 7u)) << 4));

                float d0 = 0.f, d1 = 0.f, d2 = 0.f, d3 = 0.f;
                // h_hi * Whi   (A kt 0..3, B frags from e0r/e1r)
                mma16816(d0,d1,d2,d3, a2f[0][0],a2f[0][1],a2f[0][2],a2f[0][3], e0r[0],e0r[1]);
                mma16816(d0,d1,d2,d3, a2f[1][0],a2f[1][1],a2f[1][2],a2f[1][3], e0r[2],e0r[3]);
                mma16816(d0,d1,d2,d3, a2f[2][0],a2f[2][1],a2f[2][2],a2f[2][3], e1r[0],e1r[1]);
                mma16816(d0,d1,d2,d3, a2f[3][0],a2f[3][1],a2f[3][2],a2f[3][3], e1r[2],e1r[3]);
                // h_lo * Whi   (A kt 4..7)
                mma16816(d0,d1,d2,d3, a2f[4][0],a2f[4][1],a2f[4][2],a2f[4][3], e0r[0],e0r[1]);
                mma16816(d0,d1,d2,d3, a2f[5][0],a2f[5][1],a2f[5][2],a2f[5][3], e0r[2],e0r[3]);
                mma16816(d0,d1,d2,d3, a2f[6][0],a2f[6][1],a2f[6][2],a2f[6][3], e1r[0],e1r[1]);
                mma16816(d0,d1,d2,d3, a2f[7][0],a2f[7][1],a2f[7][2],a2f[7][3], e1r[2],e1r[3]);
                // h_hi * Wlo   (A kt 0..3, B frags from f0r/f1r)
                mma16816(d0,d1,d2,d3, a2f[0][0],a2f[0][1],a2f[0][2],a2f[0][3], f0r[0],f0r[1]);
                mma16816(d0,d1,d2,d3, a2f[1][0],a2f[1][1],a2f[1][2],a2f[1][3], f0r[2],f0r[3]);
                mma16816(d0,d1,d2,d3, a2f[2][0],a2f[2][1],a2f[2][2],a2f[2][3], f1r[0],f1r[1]);
                mma16816(d0,d1,d2,d3, a2f[3][0],a2f[3][1],a2f[3][2],a2f[3][3], f1r[2],f1r[3]);

                int col0 = nt2*8 + lr2;  // permuted output col: 0..31 = rgb, 32 = sigma
                if (nt2 < 4) {
                    float v0 = __fdividef(1.002f, 1.f + __expf(-(d0 + sb2p[col0])))   - 0.001f;
                    float v1 = __fdividef(1.002f, 1.f + __expf(-(d1 + sb2p[col0+1]))) - 0.001f;
                    float v2 = __fdividef(1.002f, 1.f + __expf(-(d2 + sb2p[col0])))   - 0.001f;
                    float v3 = __fdividef(1.002f, 1.f + __expf(-(d3 + sb2p[col0+1]))) - 0.001f;
                    *(ull*)(rgb_out + (size_t)r0*32 + col0) = pack2(v0, v1);
                    *(ull*)(rgb_out + (size_t)r1*32 + col0) = pack2(v2, v3);
                } else if (lr2 == 0) {
                    // col 32 = sigma
                    sigma_out[r0] = d0 + sb2p[32];
                    sigma_out[r1] = d2 + sb2p[32];
                }
            }
        }
    }
}

// -------- warp-per-ray: coarse march weights + inverse-CDF sampling --------
__global__ void __launch_bounds__(128) k_importance(const float* __restrict__ nimp) {
    int gw   = (blockIdx.x * 128 + threadIdx.x) >> 5;
    int lane = threadIdx.x & 31;
    int wl   = threadIdx.x >> 5;
    __shared__ float sh_d[4][48], sh_s[4][48];
    __shared__ float sh_a[4][48];
    __shared__ float sh_w[4][48];
    __shared__ float sh_cdf[4][46];
    __shared__ float sh_bins[4][48];
    if (gw >= NRAY) return;

    const float* dp = g_depths_c + (size_t)gw*SC;
    const float* sp = g_sigma_c  + (size_t)gw*SC;
    for (int i = lane; i < 48; i += 32) { sh_d[wl][i] = dp[i]; sh_s[wl][i] = sp[i]; }
    __syncwarp();

    for (int i = lane; i < 47; i += 32) {
        float d0 = sh_d[wl][i], d1 = sh_d[wl][i+1];
        float dens = softplus_fast(0.5f*(sh_s[wl][i] + sh_s[wl][i+1]) - 1.f);
        sh_a[wl][i]    = 1.f - __expf(-dens*(d1 - d0));
        sh_bins[wl][i] = 0.5f*(d0 + d1);
    }
    __syncwarp();

    if (lane == 0) {
        float T = 1.f;
        for (int i = 0; i < 47; i++) {
            float a = sh_a[wl][i];
            sh_w[wl][i] = a * T;
            T *= (1.f - a + 1e-10f);
        }
    }
    __syncwarp();

    for (int j = lane; j < 45; j += 32) {
        float m1 = fmaxf(sh_w[wl][j],   sh_w[wl][j+1]);
        float m2 = fmaxf(sh_w[wl][j+1], sh_w[wl][j+2]);
        sh_a[wl][j] = 0.5f*(m1 + m2) + 0.01f + 1e-5f;
    }
    __syncwarp();

    if (lane == 0) {
        float c = 0.f;
        sh_cdf[wl][0] = 0.f;
        for (int j = 0; j < 45; j++) { c += sh_a[wl][j]; sh_cdf[wl][j+1] = c; }
        sh_w[wl][47] = c;
    }
    __syncwarp();
    float inv = __fdividef(1.f, sh_w[wl][47]);
    for (int j = lane + 1; j < 46; j += 32) sh_cdf[wl][j] *= inv;
    __syncwarp();

    const float* up = nimp + (size_t)gw*SFN;
    float* outp = g_depths_f + (size_t)gw*SFN;
    for (int j = lane; j < SFN; j += 32) {
        float u = up[j];
        int ind = 0;
#pragma unroll
        for (int t2 = 0; t2 < 46; t2++) ind += (sh_cdf[wl][t2] <= u) ? 1 : 0;
        int below = ind - 1; if (below < 0) below = 0;
        int above = ind;     if (above > 45) above = 45;
        float cb = sh_cdf[wl][below], ca = sh_cdf[wl][above];
        float bb = sh_bins[wl][below], ba = sh_bins[wl][above];
        float den = ca - cb; if (den < 1e-5f) den = 1.f;
        outp[j] = bb + (u - cb)/den * (ba - bb);
    }
}

// -------- merge, stable sort by depth, final ray march, outputs --------
__global__ void __launch_bounds__(256) k_final(float* __restrict__ out) {
    int warp = (blockIdx.x * blockDim.x + threadIdx.x) >> 5;
    int lane = threadIdx.x & 31;
    int wloc = threadIdx.x >> 5;
    __shared__ float ds[8][96];
    __shared__ float ss[8][96];
    __shared__ int   ordsh[8][96];
    if (warp >= NRAY) return;
    int ray = warp;

    for (int k = lane; k < 96; k += 32) {
        float dv, sv;
        if (k < SC) { dv = g_depths_c[(size_t)ray*SC + k]; sv = g_sigma_c[(size_t)ray*SC + k]; }
        else        { dv = g_depths_f[(size_t)ray*SFN + k - SC]; sv = g_sigma_f[(size_t)ray*SFN + k - SC]; }
        ds[wloc][k] = dv; ss[wloc][k] = sv;
    }
    __syncwarp();

    for (int k = lane; k < 96; k += 32) {
        float di = ds[wloc][k];
        int r = 0;
        for (int j = 0; j < 96; j++) {
            float dj = ds[wloc][j];
            r += (dj < di) || (dj == di && j < k);
        }
        ordsh[wloc][r] = k;
    }
    __syncwarp();

    int i0 = ordsh[wloc][0];
    float dprev = ds[wloc][i0], sprev = ss[wloc][i0];
    float cprev = (i0 < SC) ? g_rgb_c[((size_t)ray*SC + i0)*32 + lane]
                            : g_rgb_f[((size_t)ray*SFN + i0 - SC)*32 + lane];
    float T = 1.f, rgbacc = 0.f, dacc = 0.f, wt = 0.f;
    for (int i = 1; i < 96; i++) {
        int ic = ordsh[wloc][i];
        float dcur = ds[wloc][ic], scur = ss[wloc][ic];
        float ccur = (ic < SC) ? g_rgb_c[((size_t)ray*SC + ic)*32 + lane]
                               : g_rgb_f[((size_t)ray*SFN + ic - SC)*32 + lane];
        float delta = dcur - dprev;
        float dens  = softplus_fast(0.5f*(sprev + scur) - 1.f);
        float alpha = 1.f - __expf(-dens*delta);
        float wgt   = alpha * T;
        T *= (1.f - alpha + 1e-10f);
        rgbacc = fmaf(wgt, 0.5f*(cprev + ccur), rgbacc);
        dacc   = fmaf(wgt, 0.5f*(dprev + dcur), dacc);
        wt    += wgt;
        dprev = dcur; sprev = scur; cprev = ccur;
    }

    out[(size_t)ray*32 + lane] = rgbacc*2.f - 1.f;
    if (lane == 0) {
        float depth = dacc / wt;
        if (!isfinite(depth)) depth = dprev;
        out[(size_t)NRAY*32 + ray] = depth;
        out[(size_t)NRAY*33 + ray] = wt;
        out[(size_t)NRAY*34 + ray] = T;
    }
}

extern "C" void kernel_launch(void* const* d_in, const int* in_sizes, int n_in,
                              void* d_out, int out_size) {
    const float* planes = (const float*)d_in[0];
    const float* ro     = (const float*)d_in[1];
    const float* rd     = (const float*)d_in[2];
    const float* w1     = (const float*)d_in[3];
    const float* b1     = (const float*)d_in[4];
    const float* w2     = (const float*)d_in[5];
    const float* b2     = (const float*)d_in[6];
    const float* nstrat = (const float*)d_in[7];
    const float* nimp   = (const float*)d_in[8];
    float* out = (float*)d_out;

    k_transpose<<<dim3(RES*RES/32, 1, BB*3), dim3(32, 32)>>>(planes);
    k_prep<<<1, 512>>>(w1, w2);
    k_coarse_depths<<<(NSAMP + 255)/256, 256>>>(nstrat);
    k_eval_m<<<NSAMP/128, 128>>>(ro, rd, b1, b2, /*fine=*/0);
    k_importance<<<(NRAY*32)/128, 128>>>(nimp);
    k_eval_m<<<NSAMP/128, 128>>>(ro, rd, b1, b2, /*fine=*/1);
    k_final<<<(NRAY*32)/256, 256>>>(out);
}